// round 2
// baseline (speedup 1.0000x reference)
#include <cuda_runtime.h>

// Grouped GEMM: out[e] = x[e] @ w[e]^T
//   x: [E, M, K] fp32, w: [E, N, K] fp32, out: [E, M, N] fp32
// E=16, M=256, K=2048, N=8192
//
// Round 1 baseline: SIMT register-blocked fp32 GEMM.
// BM=BN=128, BK=16, 256 threads, each thread computes an 8x8 micro-tile.
// Both A and B are K-major, staged into SMEM transposed ([BK][128]) so the
// inner product loop does conflict-free LDS.128 broadcasts.

static constexpr int E_DIM = 16;
static constexpr int M_DIM = 256;
static constexpr int K_DIM = 2048;
static constexpr int N_DIM = 8192;

static constexpr int BM = 128;
static constexpr int BN = 128;
static constexpr int BK = 16;

__global__ __launch_bounds__(256, 2)
void grouped_gemm_simt(const float* __restrict__ X,
                       const float* __restrict__ W,
                       float* __restrict__ O) {
    __shared__ float As[BK][BM];
    __shared__ float Bs[BK][BN];

    const int e  = blockIdx.z;
    const int m0 = blockIdx.y * BM;
    const int n0 = blockIdx.x * BN;

    const float* A = X + (size_t)e * M_DIM * K_DIM + (size_t)m0 * K_DIM;
    const float* B = W + (size_t)e * N_DIM * K_DIM + (size_t)n0 * K_DIM;
    float*       C = O + (size_t)e * M_DIM * N_DIM;

    const int tid = threadIdx.x;
    const int tx  = tid % 16;   // n-direction, 16 threads * 8 cols = 128
    const int ty  = tid / 16;   // m-direction, 16 threads * 8 rows = 128

    // Tile-load mapping: 128 rows x 4 float4 per row = 512 vec4 loads,
    // 256 threads -> 2 per thread (rows r and r+64).
    const int lrow = tid / 4;   // 0..63
    const int lq   = tid % 4;   // which float4 within the 16-float row chunk

    float acc[8][8];
#pragma unroll
    for (int i = 0; i < 8; i++)
#pragma unroll
        for (int j = 0; j < 8; j++) acc[i][j] = 0.0f;

    for (int k0 = 0; k0 < K_DIM; k0 += BK) {
        // Stage A and B tiles into SMEM, transposed to [k][row].
#pragma unroll
        for (int h = 0; h < 2; h++) {
            const int row = lrow + h * 64;
            const float4 va = *reinterpret_cast<const float4*>(
                A + (size_t)row * K_DIM + k0 + lq * 4);
            As[lq * 4 + 0][row] = va.x;
            As[lq * 4 + 1][row] = va.y;
            As[lq * 4 + 2][row] = va.z;
            As[lq * 4 + 3][row] = va.w;
            const float4 vb = *reinterpret_cast<const float4*>(
                B + (size_t)row * K_DIM + k0 + lq * 4);
            Bs[lq * 4 + 0][row] = vb.x;
            Bs[lq * 4 + 1][row] = vb.y;
            Bs[lq * 4 + 2][row] = vb.z;
            Bs[lq * 4 + 3][row] = vb.w;
        }
        __syncthreads();

#pragma unroll
        for (int k = 0; k < BK; k++) {
            float a[8], b[8];
            *reinterpret_cast<float4*>(a)     = *reinterpret_cast<const float4*>(&As[k][ty * 8]);
            *reinterpret_cast<float4*>(a + 4) = *reinterpret_cast<const float4*>(&As[k][ty * 8 + 4]);
            *reinterpret_cast<float4*>(b)     = *reinterpret_cast<const float4*>(&Bs[k][tx * 8]);
            *reinterpret_cast<float4*>(b + 4) = *reinterpret_cast<const float4*>(&Bs[k][tx * 8 + 4]);
#pragma unroll
            for (int i = 0; i < 8; i++)
#pragma unroll
                for (int j = 0; j < 8; j++)
                    acc[i][j] = fmaf(a[i], b[j], acc[i][j]);
        }
        __syncthreads();
    }

    // Writeback: two float4 stores per row of the 8x8 micro-tile.
#pragma unroll
    for (int i = 0; i < 8; i++) {
        float* crow = C + (size_t)(m0 + ty * 8 + i) * N_DIM + (n0 + tx * 8);
        float4 v0 = make_float4(acc[i][0], acc[i][1], acc[i][2], acc[i][3]);
        float4 v1 = make_float4(acc[i][4], acc[i][5], acc[i][6], acc[i][7]);
        *reinterpret_cast<float4*>(crow)     = v0;
        *reinterpret_cast<float4*>(crow + 4) = v1;
    }
}

extern "C" void kernel_launch(void* const* d_in, const int* in_sizes, int n_in,
                              void* d_out, int out_size) {
    const float* X = (const float*)d_in[0];  // expert_inputs  [E, M, K]
    const float* W = (const float*)d_in[1];  // expert_weights [E, N, K]
    float* O = (float*)d_out;                // [E, M, N]

    dim3 grid(N_DIM / BN, M_DIM / BM, E_DIM);  // (64, 2, 16) = 2048 CTAs
    grouped_gemm_simt<<<grid, 256>>>(X, W, O);
}

// round 5
// speedup vs baseline: 2.3705x; 2.3705x over previous
#include <cuda_runtime.h>
#include <cuda_bf16.h>
#include <stdint.h>

// Grouped GEMM out[e] = x[e] @ w[e]^T, fp32 I/O, via mma.sync bf16 (HMMA)
// with hi/lo fp32 split (3 passes: Ahi*Bhi + Ahi*Blo + Alo*Bhi).
//   x: [E, M, K], w: [E, N, K], out: [E, M, N]; E=16, M=256, K=2048, N=8192.
// CTA: 128x128 tile, 8 warps (2x4), warp tile 64x32, K-chunks of 32 fp32,
// double-buffered SMEM with 80B-padded rows (16B-aligned rows for ldmatrix;
// 80*r mod 128 covers all eight 16B segments -> conflict-free ldmatrix).

static constexpr int E_DIM = 16;
static constexpr int M_DIM = 256;
static constexpr int K_DIM = 2048;
static constexpr int N_DIM = 8192;

static constexpr int BM = 128;
static constexpr int BN = 128;
static constexpr int KC = 32;                 // fp32 k per chunk
static constexpr int NCHUNK = K_DIM / KC;     // 64

static constexpr int ROW_B   = 80;            // 32 bf16 (64 B) + 16 B pad, 16B-aligned
static constexpr int TILE_B  = 128 * ROW_B;   // 10240 B per bf16 tile
static constexpr int STAGE_B = 4 * TILE_B;    // Ahi, Alo, Bhi, Blo = 40960 B
static constexpr int SMEM_B  = 2 * STAGE_B;   // 81920 B

__device__ __forceinline__ uint32_t smem_u32(const void* p) {
    uint32_t a;
    asm("{ .reg .u64 t; cvta.to.shared.u64 t, %1; cvt.u32.u64 %0, t; }"
        : "=r"(a) : "l"(p));
    return a;
}

// Pack (x,y) into bf16x2 hi limb and bf16x2 lo (residual) limb. x -> low half.
__device__ __forceinline__ void split2(float x, float y, uint32_t& hi, uint32_t& lo) {
    __nv_bfloat162 h = __floats2bfloat162_rn(x, y);
    hi = *reinterpret_cast<uint32_t*>(&h);
    float hx = __uint_as_float(hi << 16);
    float hy = __uint_as_float(hi & 0xffff0000u);
    __nv_bfloat162 l = __floats2bfloat162_rn(x - hx, y - hy);
    lo = *reinterpret_cast<uint32_t*>(&l);
}

__device__ __forceinline__ void ldsm4(uint32_t* r, uint32_t addr) {
    asm volatile("ldmatrix.sync.aligned.m8n8.x4.shared.b16 {%0,%1,%2,%3}, [%4];"
                 : "=r"(r[0]), "=r"(r[1]), "=r"(r[2]), "=r"(r[3]) : "r"(addr));
}

__device__ __forceinline__ void mma16816(float* c, const uint32_t* a,
                                         const uint32_t* b) {
    asm volatile(
        "mma.sync.aligned.m16n8k16.row.col.f32.bf16.bf16.f32 "
        "{%0,%1,%2,%3}, {%4,%5,%6,%7}, {%8,%9}, {%0,%1,%2,%3};"
        : "+f"(c[0]), "+f"(c[1]), "+f"(c[2]), "+f"(c[3])
        : "r"(a[0]), "r"(a[1]), "r"(a[2]), "r"(a[3]), "r"(b[0]), "r"(b[1]));
}

__global__ __launch_bounds__(256, 1)
void grouped_gemm_hmma(const float* __restrict__ X,
                       const float* __restrict__ W,
                       float* __restrict__ O) {
    extern __shared__ char sm[];
    const uint32_t sbase = smem_u32(sm);

    const int tid  = threadIdx.x;
    const int wid  = tid >> 5;
    const int lane = tid & 31;
    const int wm   = wid >> 2;   // 0..1 -> 64-row slab
    const int wn   = wid & 3;    // 0..3 -> 32-col slab

    const int e  = blockIdx.z;
    const int m0 = blockIdx.y * BM;
    const int n0 = blockIdx.x * BN;

    // ---- global load mapping: 2 threads per row, 16 floats each ----
    const int grow = tid >> 1;      // 0..127
    const int ghalf = tid & 1;      // 16-float half of the 32-wide chunk
    const float* Ag = X + ((size_t)e * M_DIM + m0 + grow) * K_DIM + ghalf * 16;
    const float* Bg = W + ((size_t)e * N_DIM + n0 + grow) * K_DIM + ghalf * 16;
    const uint32_t wb = grow * ROW_B + ghalf * 32;   // smem byte base for stores

    // ---- ldmatrix address offsets (within a tile) ----
    // A (m16k16 x4): row = wm*64 + mt*16 + (lane&15), col16B = lane>>4
    const uint32_t aoff = (uint32_t)((wm * 64 + (lane & 15)) * ROW_B + ((lane >> 4) << 4));
    // B (two n8k16 tiles per x4): row = wn*32 + np*16 + ((lane>>4)<<3) + (lane&7),
    //                             col16B = (lane>>3)&1
    const uint32_t boff = (uint32_t)((wn * 32 + ((lane >> 4) << 3) + (lane & 7)) * ROW_B
                                     + (((lane >> 3) & 1) << 4));

    float acc[4][4][4];
#pragma unroll
    for (int i = 0; i < 4; i++)
#pragma unroll
        for (int j = 0; j < 4; j++)
#pragma unroll
            for (int v = 0; v < 4; v++) acc[i][j][v] = 0.0f;

    float4 av[4], bv[4];

    // prologue: chunk 0 -> stage 0
#pragma unroll
    for (int j = 0; j < 4; j++) {
        av[j] = *reinterpret_cast<const float4*>(Ag + j * 4);
        bv[j] = *reinterpret_cast<const float4*>(Bg + j * 4);
    }
    {
        char* ah = sm + 0 * TILE_B; char* al = sm + 1 * TILE_B;
        char* bh = sm + 2 * TILE_B; char* bl = sm + 3 * TILE_B;
#pragma unroll
        for (int j = 0; j < 4; j++) {
            uint32_t h0, l0, h1, l1;
            split2(av[j].x, av[j].y, h0, l0);
            split2(av[j].z, av[j].w, h1, l1);
            *reinterpret_cast<uint2*>(ah + wb + j * 8) = make_uint2(h0, h1);
            *reinterpret_cast<uint2*>(al + wb + j * 8) = make_uint2(l0, l1);
            split2(bv[j].x, bv[j].y, h0, l0);
            split2(bv[j].z, bv[j].w, h1, l1);
            *reinterpret_cast<uint2*>(bh + wb + j * 8) = make_uint2(h0, h1);
            *reinterpret_cast<uint2*>(bl + wb + j * 8) = make_uint2(l0, l1);
        }
    }
    __syncthreads();

#pragma unroll 1
    for (int c = 0; c < NCHUNK; c++) {
        // issue next chunk's loads early (latency hides under the MMAs)
        if (c + 1 < NCHUNK) {
            const int kof = (c + 1) * KC;
#pragma unroll
            for (int j = 0; j < 4; j++) {
                av[j] = *reinterpret_cast<const float4*>(Ag + kof + j * 4);
                bv[j] = *reinterpret_cast<const float4*>(Bg + kof + j * 4);
            }
        }

        // ---- compute from stage c&1 ----
        const uint32_t st = sbase + (uint32_t)((c & 1) * STAGE_B);
        const uint32_t Ahi = st, Alo = st + TILE_B, Bhi = st + 2 * TILE_B, Blo = st + 3 * TILE_B;

#pragma unroll
        for (int ks = 0; ks < 2; ks++) {
            const uint32_t ksb = ks * 32;
            uint32_t ah[4][4], al[4][4], bh[8], bl[8];
#pragma unroll
            for (int mt = 0; mt < 4; mt++) {
                ldsm4(ah[mt], Ahi + aoff + mt * (16 * ROW_B) + ksb);
                ldsm4(al[mt], Alo + aoff + mt * (16 * ROW_B) + ksb);
            }
#pragma unroll
            for (int np = 0; np < 2; np++) {
                ldsm4(bh + np * 4, Bhi + boff + np * (16 * ROW_B) + ksb);
                ldsm4(bl + np * 4, Blo + boff + np * (16 * ROW_B) + ksb);
            }
            // pass 1: Ahi * Bhi
#pragma unroll
            for (int mt = 0; mt < 4; mt++)
#pragma unroll
                for (int nt = 0; nt < 4; nt++)
                    mma16816(acc[mt][nt], ah[mt], bh + 2 * nt);
            // pass 2: Ahi * Blo
#pragma unroll
            for (int mt = 0; mt < 4; mt++)
#pragma unroll
                for (int nt = 0; nt < 4; nt++)
                    mma16816(acc[mt][nt], ah[mt], bl + 2 * nt);
            // pass 3: Alo * Bhi
#pragma unroll
            for (int mt = 0; mt < 4; mt++)
#pragma unroll
                for (int nt = 0; nt < 4; nt++)
                    mma16816(acc[mt][nt], al[mt], bh + 2 * nt);
        }

        // ---- store next chunk into stage (c+1)&1 ----
        if (c + 1 < NCHUNK) {
            char* dst = sm + ((c + 1) & 1) * STAGE_B;
            char* ah = dst + 0 * TILE_B; char* al = dst + 1 * TILE_B;
            char* bh = dst + 2 * TILE_B; char* bl = dst + 3 * TILE_B;
#pragma unroll
            for (int j = 0; j < 4; j++) {
                uint32_t h0, l0, h1, l1;
                split2(av[j].x, av[j].y, h0, l0);
                split2(av[j].z, av[j].w, h1, l1);
                *reinterpret_cast<uint2*>(ah + wb + j * 8) = make_uint2(h0, h1);
                *reinterpret_cast<uint2*>(al + wb + j * 8) = make_uint2(l0, l1);
                split2(bv[j].x, bv[j].y, h0, l0);
                split2(bv[j].z, bv[j].w, h1, l1);
                *reinterpret_cast<uint2*>(bh + wb + j * 8) = make_uint2(h0, h1);
                *reinterpret_cast<uint2*>(bl + wb + j * 8) = make_uint2(l0, l1);
            }
        }
        __syncthreads();
    }

    // ---- epilogue: acc frag layout -> fp32 stores (float2, sector-aligned) ----
    float* C = O + (size_t)e * M_DIM * N_DIM;
    const int mrow = m0 + wm * 64 + (lane >> 2);
    const int ncol = n0 + wn * 32 + (lane & 3) * 2;
#pragma unroll
    for (int mt = 0; mt < 4; mt++) {
#pragma unroll
        for (int nt = 0; nt < 4; nt++) {
            float* p0 = C + (size_t)(mrow + mt * 16) * N_DIM + (ncol + nt * 8);
            float* p1 = p0 + 8 * N_DIM;
            *reinterpret_cast<float2*>(p0) = make_float2(acc[mt][nt][0], acc[mt][nt][1]);
            *reinterpret_cast<float2*>(p1) = make_float2(acc[mt][nt][2], acc[mt][nt][3]);
        }
    }
}

extern "C" void kernel_launch(void* const* d_in, const int* in_sizes, int n_in,
                              void* d_out, int out_size) {
    const float* X = (const float*)d_in[0];  // expert_inputs  [E, M, K]
    const float* W = (const float*)d_in[1];  // expert_weights [E, N, K]
    float* O = (float*)d_out;                // [E, M, N]

    cudaFuncSetAttribute(grouped_gemm_hmma,
                         cudaFuncAttributeMaxDynamicSharedMemorySize, SMEM_B);

    dim3 grid(N_DIM / BN, M_DIM / BM, E_DIM);  // (64, 2, 16) = 2048 CTAs
    grouped_gemm_hmma<<<grid, 256, SMEM_B>>>(X, W, O);
}

// round 6
// speedup vs baseline: 2.3729x; 1.0010x over previous
#include <cuda_runtime.h>
#include <cuda_bf16.h>
#include <stdint.h>

// Grouped GEMM out[e] = x[e] @ w[e]^T, fp32 I/O, via mma.sync bf16 (HMMA)
// with hi/lo fp32 split (3 passes: Ahi*Bhi + Ahi*Blo + Alo*Bhi).
//   x: [E, M, K], w: [E, N, K], out: [E, M, N]; E=16, M=256, K=2048, N=8192.
// CTA: 128x128 tile, 8 warps (2x4), warp tile 64x32, K-chunks of 32 fp32,
// double-buffered SMEM with 80B-padded rows (16B-aligned rows for ldmatrix;
// 80*r mod 128 covers all eight 16B segments -> conflict-free ldmatrix).

static constexpr int E_DIM = 16;
static constexpr int M_DIM = 256;
static constexpr int K_DIM = 2048;
static constexpr int N_DIM = 8192;

static constexpr int BM = 128;
static constexpr int BN = 128;
static constexpr int KC = 32;                 // fp32 k per chunk
static constexpr int NCHUNK = K_DIM / KC;     // 64

static constexpr int ROW_B   = 80;            // 32 bf16 (64 B) + 16 B pad, 16B-aligned
static constexpr int TILE_B  = 128 * ROW_B;   // 10240 B per bf16 tile
static constexpr int STAGE_B = 4 * TILE_B;    // Ahi, Alo, Bhi, Blo = 40960 B
static constexpr int SMEM_B  = 2 * STAGE_B;   // 81920 B

__device__ __forceinline__ uint32_t smem_u32(const void* p) {
    uint32_t a;
    asm("{ .reg .u64 t; cvta.to.shared.u64 t, %1; cvt.u32.u64 %0, t; }"
        : "=r"(a) : "l"(p));
    return a;
}

// Pack (x,y) into bf16x2 hi limb and bf16x2 lo (residual) limb. x -> low half.
__device__ __forceinline__ void split2(float x, float y, uint32_t& hi, uint32_t& lo) {
    __nv_bfloat162 h = __floats2bfloat162_rn(x, y);
    hi = *reinterpret_cast<uint32_t*>(&h);
    float hx = __uint_as_float(hi << 16);
    float hy = __uint_as_float(hi & 0xffff0000u);
    __nv_bfloat162 l = __floats2bfloat162_rn(x - hx, y - hy);
    lo = *reinterpret_cast<uint32_t*>(&l);
}

__device__ __forceinline__ void ldsm4(uint32_t* r, uint32_t addr) {
    asm volatile("ldmatrix.sync.aligned.m8n8.x4.shared.b16 {%0,%1,%2,%3}, [%4];"
                 : "=r"(r[0]), "=r"(r[1]), "=r"(r[2]), "=r"(r[3]) : "r"(addr));
}

__device__ __forceinline__ void mma16816(float* c, const uint32_t* a,
                                         const uint32_t* b) {
    asm volatile(
        "mma.sync.aligned.m16n8k16.row.col.f32.bf16.bf16.f32 "
        "{%0,%1,%2,%3}, {%4,%5,%6,%7}, {%8,%9}, {%0,%1,%2,%3};"
        : "+f"(c[0]), "+f"(c[1]), "+f"(c[2]), "+f"(c[3])
        : "r"(a[0]), "r"(a[1]), "r"(a[2]), "r"(a[3]), "r"(b[0]), "r"(b[1]));
}

__global__ __launch_bounds__(256, 1)
void grouped_gemm_hmma(const float* __restrict__ X,
                       const float* __restrict__ W,
                       float* __restrict__ O) {
    extern __shared__ char sm[];
    const uint32_t sbase = smem_u32(sm);

    const int tid  = threadIdx.x;
    const int wid  = tid >> 5;
    const int lane = tid & 31;
    const int wm   = wid >> 2;   // 0..1 -> 64-row slab
    const int wn   = wid & 3;    // 0..3 -> 32-col slab

    const int e  = blockIdx.z;
    const int m0 = blockIdx.y * BM;
    const int n0 = blockIdx.x * BN;

    // ---- global load mapping: 2 threads per row, 16 floats each ----
    const int grow = tid >> 1;      // 0..127
    const int ghalf = tid & 1;      // 16-float half of the 32-wide chunk
    const float* Ag = X + ((size_t)e * M_DIM + m0 + grow) * K_DIM + ghalf * 16;
    const float* Bg = W + ((size_t)e * N_DIM + n0 + grow) * K_DIM + ghalf * 16;
    const uint32_t wb = grow * ROW_B + ghalf * 32;   // smem byte base for stores

    // ---- ldmatrix address offsets (within a tile) ----
    // A (m16k16 x4): row = wm*64 + mt*16 + (lane&15), col16B = lane>>4
    const uint32_t aoff = (uint32_t)((wm * 64 + (lane & 15)) * ROW_B + ((lane >> 4) << 4));
    // B (two n8k16 tiles per x4): row = wn*32 + np*16 + ((lane>>4)<<3) + (lane&7),
    //                             col16B = (lane>>3)&1
    const uint32_t boff = (uint32_t)((wn * 32 + ((lane >> 4) << 3) + (lane & 7)) * ROW_B
                                     + (((lane >> 3) & 1) << 4));

    float acc[4][4][4];
#pragma unroll
    for (int i = 0; i < 4; i++)
#pragma unroll
        for (int j = 0; j < 4; j++)
#pragma unroll
            for (int v = 0; v < 4; v++) acc[i][j][v] = 0.0f;

    float4 av[4], bv[4];

    // prologue: chunk 0 -> stage 0
#pragma unroll
    for (int j = 0; j < 4; j++) {
        av[j] = *reinterpret_cast<const float4*>(Ag + j * 4);
        bv[j] = *reinterpret_cast<const float4*>(Bg + j * 4);
    }
    {
        char* ah = sm + 0 * TILE_B; char* al = sm + 1 * TILE_B;
        char* bh = sm + 2 * TILE_B; char* bl = sm + 3 * TILE_B;
#pragma unroll
        for (int j = 0; j < 4; j++) {
            uint32_t h0, l0, h1, l1;
            split2(av[j].x, av[j].y, h0, l0);
            split2(av[j].z, av[j].w, h1, l1);
            *reinterpret_cast<uint2*>(ah + wb + j * 8) = make_uint2(h0, h1);
            *reinterpret_cast<uint2*>(al + wb + j * 8) = make_uint2(l0, l1);
            split2(bv[j].x, bv[j].y, h0, l0);
            split2(bv[j].z, bv[j].w, h1, l1);
            *reinterpret_cast<uint2*>(bh + wb + j * 8) = make_uint2(h0, h1);
            *reinterpret_cast<uint2*>(bl + wb + j * 8) = make_uint2(l0, l1);
        }
    }
    __syncthreads();

#pragma unroll 1
    for (int c = 0; c < NCHUNK; c++) {
        // issue next chunk's loads early (latency hides under the MMAs)
        if (c + 1 < NCHUNK) {
            const int kof = (c + 1) * KC;
#pragma unroll
            for (int j = 0; j < 4; j++) {
                av[j] = *reinterpret_cast<const float4*>(Ag + kof + j * 4);
                bv[j] = *reinterpret_cast<const float4*>(Bg + kof + j * 4);
            }
        }

        // ---- compute from stage c&1 ----
        const uint32_t st = sbase + (uint32_t)((c & 1) * STAGE_B);
        const uint32_t Ahi = st, Alo = st + TILE_B, Bhi = st + 2 * TILE_B, Blo = st + 3 * TILE_B;

#pragma unroll
        for (int ks = 0; ks < 2; ks++) {
            const uint32_t ksb = ks * 32;
            uint32_t ah[4][4], al[4][4], bh[8], bl[8];
#pragma unroll
            for (int mt = 0; mt < 4; mt++) {
                ldsm4(ah[mt], Ahi + aoff + mt * (16 * ROW_B) + ksb);
                ldsm4(al[mt], Alo + aoff + mt * (16 * ROW_B) + ksb);
            }
#pragma unroll
            for (int np = 0; np < 2; np++) {
                ldsm4(bh + np * 4, Bhi + boff + np * (16 * ROW_B) + ksb);
                ldsm4(bl + np * 4, Blo + boff + np * (16 * ROW_B) + ksb);
            }
            // pass 1: Ahi * Bhi
#pragma unroll
            for (int mt = 0; mt < 4; mt++)
#pragma unroll
                for (int nt = 0; nt < 4; nt++)
                    mma16816(acc[mt][nt], ah[mt], bh + 2 * nt);
            // pass 2: Ahi * Blo
#pragma unroll
            for (int mt = 0; mt < 4; mt++)
#pragma unroll
                for (int nt = 0; nt < 4; nt++)
                    mma16816(acc[mt][nt], ah[mt], bl + 2 * nt);
            // pass 3: Alo * Bhi
#pragma unroll
            for (int mt = 0; mt < 4; mt++)
#pragma unroll
                for (int nt = 0; nt < 4; nt++)
                    mma16816(acc[mt][nt], al[mt], bh + 2 * nt);
        }

        // ---- store next chunk into stage (c+1)&1 ----
        if (c + 1 < NCHUNK) {
            char* dst = sm + ((c + 1) & 1) * STAGE_B;
            char* ah = dst + 0 * TILE_B; char* al = dst + 1 * TILE_B;
            char* bh = dst + 2 * TILE_B; char* bl = dst + 3 * TILE_B;
#pragma unroll
            for (int j = 0; j < 4; j++) {
                uint32_t h0, l0, h1, l1;
                split2(av[j].x, av[j].y, h0, l0);
                split2(av[j].z, av[j].w, h1, l1);
                *reinterpret_cast<uint2*>(ah + wb + j * 8) = make_uint2(h0, h1);
                *reinterpret_cast<uint2*>(al + wb + j * 8) = make_uint2(l0, l1);
                split2(bv[j].x, bv[j].y, h0, l0);
                split2(bv[j].z, bv[j].w, h1, l1);
                *reinterpret_cast<uint2*>(bh + wb + j * 8) = make_uint2(h0, h1);
                *reinterpret_cast<uint2*>(bl + wb + j * 8) = make_uint2(l0, l1);
            }
        }
        __syncthreads();
    }

    // ---- epilogue: acc frag layout -> fp32 stores (float2, sector-aligned) ----
    float* C = O + (size_t)e * M_DIM * N_DIM;
    const int mrow = m0 + wm * 64 + (lane >> 2);
    const int ncol = n0 + wn * 32 + (lane & 3) * 2;
#pragma unroll
    for (int mt = 0; mt < 4; mt++) {
#pragma unroll
        for (int nt = 0; nt < 4; nt++) {
            float* p0 = C + (size_t)(mrow + mt * 16) * N_DIM + (ncol + nt * 8);
            float* p1 = p0 + 8 * N_DIM;
            *reinterpret_cast<float2*>(p0) = make_float2(acc[mt][nt][0], acc[mt][nt][1]);
            *reinterpret_cast<float2*>(p1) = make_float2(acc[mt][nt][2], acc[mt][nt][3]);
        }
    }
}

extern "C" void kernel_launch(void* const* d_in, const int* in_sizes, int n_in,
                              void* d_out, int out_size) {
    const float* X = (const float*)d_in[0];  // expert_inputs  [E, M, K]
    const float* W = (const float*)d_in[1];  // expert_weights [E, N, K]
    float* O = (float*)d_out;                // [E, M, N]

    cudaFuncSetAttribute(grouped_gemm_hmma,
                         cudaFuncAttributeMaxDynamicSharedMemorySize, SMEM_B);

    dim3 grid(N_DIM / BN, M_DIM / BM, E_DIM);  // (64, 2, 16) = 2048 CTAs
    grouped_gemm_hmma<<<grid, 256, SMEM_B>>>(X, W, O);
}